// round 8
// baseline (speedup 1.0000x reference)
#include <cuda_runtime.h>
#include <cstdint>

#define Bdim 4
#define Hdim 512
#define Wdim 512
#define C_TOTAL 25
#define CS (Hdim * Wdim)

typedef unsigned long long u64;

// All layer weights (oc-major per layer) + biases in constant memory.
// Layer L offset: 18*L*L floats (since sum_{k<L} 18*(2k+1) = 18 L^2). Total 2592.
__constant__ float cw[2592];
__constant__ float cb[24];

__device__ __forceinline__ void fma2(u64& d, u64 a, u64 b) {
    asm("fma.rn.f32x2 %0, %1, %2, %0;" : "+l"(d) : "l"(a), "l"(b));
}
__device__ __forceinline__ u64 dup2(float v) {
    u64 r; asm("mov.b64 %0, {%1, %1};" : "=l"(r) : "f"(v)); return r;
}
__device__ __forceinline__ u64 pack2(float lo, float hi) {
    u64 r; asm("mov.b64 %0, {%1, %2};" : "=l"(r) : "f"(lo), "f"(hi)); return r;
}
__device__ __forceinline__ void unpack2(u64 v, float& lo, float& hi) {
    asm("mov.b64 {%0, %1}, %2;" : "=f"(lo), "=f"(hi) : "l"(v));
}
__device__ __forceinline__ int refl(int x) {        // reflect for H == W == 512
    return x < 0 ? -x : (x >= 512 ? 1022 - x : x);
}

// ---------------------------------------------------------------------------
// EVEN-D layers: column-pair f32x2 taps (3 aligned LDG.64 per row), R=8 rows.
// Warp = 8 rows x 64 cols. Block = 256 thr = 8 row-groups (64x64 tile).
// Grid (8,8,4) = 256 blocks * 8 warps = 2048 warps.
// ---------------------------------------------------------------------------
template<int L, int N_IN, int D, bool EDGE>
__device__ __forceinline__ void tile_even(const float* __restrict__ g,
                                          float* __restrict__ outg,
                                          int w, int r0, int b)
{
    constexpr int R = 8;
    constexpr int OFF = 18 * L * L;

    u64 accA[R], accB[R];
    {
        u64 bA = dup2(cb[2 * L]), bB = dup2(cb[2 * L + 1]);
        #pragma unroll
        for (int m = 0; m < R; ++m) { accA[m] = bA; accB[m] = bB; }
    }

    const float* plane0 = g + (size_t)(b * C_TOTAL) * CS;

    #pragma unroll 1
    for (int ic = 0; ic < N_IN; ++ic) {
        const float* plane = plane0 + (size_t)ic * CS;
        u64 wA[9], wB[9];
        #pragma unroll
        for (int k = 0; k < 9; ++k) {
            wA[k] = dup2(cw[OFF + ic * 9 + k]);
            wB[k] = dup2(cw[OFF + 9 * N_IN + ic * 9 + k]);
        }

        #pragma unroll
        for (int j = 0; j < R + 2 * D; ++j) {
            const float* row = plane + ((size_t)refl(r0 - D + j) << 9);
            u64 vc = *(const u64*)(row + w);               // w even -> aligned
            u64 vl, vr;
            if (EDGE) {
                vl = pack2(row[refl(w - D)], row[refl(w + 1 - D)]);
                vr = pack2(row[refl(w + D)], row[refl(w + 1 + D)]);
            } else {
                vl = *(const u64*)(row + (w - D));          // D even -> aligned
                vr = *(const u64*)(row + (w + D));
            }
            if (j < R) {
                fma2(accA[j], wA[0], vl); fma2(accA[j], wA[1], vc); fma2(accA[j], wA[2], vr);
                fma2(accB[j], wB[0], vl); fma2(accB[j], wB[1], vc); fma2(accB[j], wB[2], vr);
            }
            if (j >= D && j < R + D) {
                fma2(accA[j - D], wA[3], vl); fma2(accA[j - D], wA[4], vc); fma2(accA[j - D], wA[5], vr);
                fma2(accB[j - D], wB[3], vl); fma2(accB[j - D], wB[4], vc); fma2(accB[j - D], wB[5], vr);
            }
            if (j >= 2 * D) {
                fma2(accA[j - 2 * D], wA[6], vl); fma2(accA[j - 2 * D], wA[7], vc); fma2(accA[j - 2 * D], wA[8], vr);
                fma2(accB[j - 2 * D], wB[6], vl); fma2(accB[j - 2 * D], wB[7], vc); fma2(accB[j - 2 * D], wB[8], vr);
            }
        }
    }

    float* o = outg + ((size_t)(b * C_TOTAL + N_IN)) * CS + (size_t)r0 * Wdim + w;
    #pragma unroll
    for (int m = 0; m < R; ++m) {
        float lo, hi;
        unpack2(accA[m], lo, hi);
        *(float2*)(o + (size_t)m * Wdim) = make_float2(fmaxf(lo, 0.f), fmaxf(hi, 0.f));
        unpack2(accB[m], lo, hi);
        *(float2*)(o + CS + (size_t)m * Wdim) = make_float2(fmaxf(lo, 0.f), fmaxf(hi, 0.f));
    }
}

template<int L, int N_IN, int D>
__global__ __launch_bounds__(256, 2)
void conv_even(const float* __restrict__ g, float* __restrict__ outg)
{
    const int tc = threadIdx.x & 31;
    const int rg = threadIdx.x >> 5;
    const int w  = blockIdx.x * 64 + 2 * tc;
    const int r0 = blockIdx.y * 64 + rg * 8;
    const int b  = blockIdx.z;

    if (blockIdx.x == 0 || blockIdx.x == 7)
        tile_even<L, N_IN, D, true >(g, outg, w, r0, b);
    else
        tile_even<L, N_IN, D, false>(g, outg, w, r0, b);
}

// ---------------------------------------------------------------------------
// ODD-D layers: scalar column, out-channel-pair f32x2 acc (3 LDG.32 per row),
// R=16 rows. Warp = 16 rows x 32 cols. Block = 256 thr = 8 row-groups
// (128x32 tile). Grid (16,4,4) = 256 blocks * 8 warps = 2048 warps.
// ---------------------------------------------------------------------------
template<int L, int N_IN, int D>
__global__ __launch_bounds__(256, 2)
void conv_odd(const float* __restrict__ g, float* __restrict__ outg)
{
    constexpr int R = 16;
    constexpr int OFF = 18 * L * L;

    const int tc = threadIdx.x & 31;
    const int rg = threadIdx.x >> 5;
    const int w  = blockIdx.x * 32 + tc;
    const int r0 = blockIdx.y * 128 + rg * R;
    const int b  = blockIdx.z;

    const int wl = refl(w - D);
    const int wr = refl(w + D);

    u64 acc[R];
    {
        u64 bp = pack2(cb[2 * L], cb[2 * L + 1]);
        #pragma unroll
        for (int m = 0; m < R; ++m) acc[m] = bp;
    }

    const float* plane0 = g + (size_t)(b * C_TOTAL) * CS;

    #pragma unroll 1
    for (int ic = 0; ic < N_IN; ++ic) {
        const float* plane = plane0 + (size_t)ic * CS;
        u64 wp[9];
        #pragma unroll
        for (int k = 0; k < 9; ++k)
            wp[k] = pack2(cw[OFF + ic * 9 + k], cw[OFF + 9 * N_IN + ic * 9 + k]);

        #pragma unroll
        for (int j = 0; j < R + 2 * D; ++j) {
            const float* row = plane + ((size_t)refl(r0 - D + j) << 9);
            u64 vl = dup2(row[wl]);
            u64 vc = dup2(row[w]);
            u64 vr = dup2(row[wr]);
            if (j < R) {
                fma2(acc[j], wp[0], vl); fma2(acc[j], wp[1], vc); fma2(acc[j], wp[2], vr);
            }
            if (j >= D && j < R + D) {
                fma2(acc[j - D], wp[3], vl); fma2(acc[j - D], wp[4], vc); fma2(acc[j - D], wp[5], vr);
            }
            if (j >= 2 * D) {
                fma2(acc[j - 2 * D], wp[6], vl); fma2(acc[j - 2 * D], wp[7], vc); fma2(acc[j - 2 * D], wp[8], vr);
            }
        }
    }

    float* o = outg + ((size_t)(b * C_TOTAL + N_IN)) * CS + (size_t)r0 * Wdim + w;
    #pragma unroll
    for (int m = 0; m < R; ++m) {
        float lo, hi;
        unpack2(acc[m], lo, hi);
        o[(size_t)m * Wdim]      = fmaxf(lo, 0.f);
        o[CS + (size_t)m * Wdim] = fmaxf(hi, 0.f);
    }
}

__global__ void copy_in_kernel(const float4* __restrict__ x, float4* __restrict__ out) {
    int idx = blockIdx.x * blockDim.x + threadIdx.x;
    const int P4 = CS / 4;
    if (idx >= Bdim * P4) return;
    int b = idx / P4;
    int p = idx - b * P4;
    out[(size_t)b * (C_TOTAL * P4) + p] = x[idx];
}

extern "C" void kernel_launch(void* const* d_in, const int* in_sizes, int n_in,
                              void* d_out, int out_size) {
    const float* x = (const float*)d_in[0];
    float* out = (float*)d_out;

    // Stage weights + bias into constant memory (D2D async copies: capture-legal).
    for (int i = 0; i < 12; ++i) {
        int nin = 1 + 2 * i;
        cudaMemcpyToSymbolAsync(cw, d_in[2 + i], (size_t)(18 * nin) * 4,
                                (size_t)(18 * i * i) * 4, cudaMemcpyDeviceToDevice, 0);
    }
    cudaMemcpyToSymbolAsync(cb, d_in[1], 24 * 4, 0, cudaMemcpyDeviceToDevice, 0);

    {
        int total4 = Bdim * CS / 4;
        copy_in_kernel<<<(total4 + 255) / 256, 256>>>((const float4*)x, (float4*)out);
    }

    const dim3 ge(8, 8, Bdim);    // even-D: 64x64 tiles
    const dim3 go(16, 4, Bdim);   // odd-D : 32x128 tiles

    conv_odd <0,  1,  1><<<go, 256>>>(out, out);
    conv_even<1,  3,  2><<<ge, 256>>>(out, out);
    conv_odd <2,  5,  3><<<go, 256>>>(out, out);
    conv_even<3,  7,  4><<<ge, 256>>>(out, out);
    conv_odd <4,  9,  5><<<go, 256>>>(out, out);
    conv_even<5, 11,  6><<<ge, 256>>>(out, out);
    conv_odd <6, 13,  7><<<go, 256>>>(out, out);
    conv_even<7, 15,  8><<<ge, 256>>>(out, out);
    conv_odd <8, 17,  9><<<go, 256>>>(out, out);
    conv_even<9, 19, 10><<<ge, 256>>>(out, out);
    conv_odd <10, 21, 11><<<go, 256>>>(out, out);
    conv_even<11, 23, 12><<<ge, 256>>>(out, out);
}